// round 6
// baseline (speedup 1.0000x reference)
#include <cuda_runtime.h>
#include <cstdint>

// MeanAggregatorHead: out[b,:] = (1/K) * sum_k tab[idx[b,k],:]
// B=100000, K=32, N=500000, D=128, fp32 table, int32 indices.
//
// Phase-sequential persistent kernel, SMEM accumulators.
// Two sequential launches, each handling half the batch with accumulators
// fully resident in shared memory (169 nodes * 512B = 86.5KB/CTA, 296 CTAs
// = one wave, 2 CTAs/SM). The table is swept in 4 phases of 64MB so the
// active chunk is L2-resident chip-wide. No partial-sum global traffic at
// all (that cost R3/R4 ~150MB of L2 bytes). Floor: 1.7GB L2 / 11.3TB/s LTS
// cap ~ 150us.

constexpr int K       = 32;
constexpr int D       = 128;
constexpr int THREADS = 512;   // 16 warps
constexpr int NPC     = 169;   // nodes per CTA  (169*512B = 86,528B smem)
constexpr int PHASES  = 4;     // 125000-row (64MB) table chunks

__global__ __launch_bounds__(THREADS, 2) void mean_agg_phased(
    const float* __restrict__ tab,
    const int*   __restrict__ idx,
    float* __restrict__ out,
    int nodeBase, int nodeEnd, int N)
{
    extern __shared__ float4 sacc[];          // NPC * 32 float4
    int tid  = threadIdx.x;
    int w    = tid >> 5;
    int lane = tid & 31;

    // Zero accumulators.
    for (int i = tid; i < NPC * 32; i += THREADS)
        sacc[i] = make_float4(0.f, 0.f, 0.f, 0.f);
    __syncthreads();

    int ctaBase = nodeBase + blockIdx.x * NPC;
    int chunk   = (N + PHASES - 1) / PHASES;

    for (int p = 0; p < PHASES; ++p) {
        int lo = p * chunk;
        int hi = min(lo + chunk, N);

        for (int n = w; n < NPC; n += THREADS / 32) {   // warp owns node n
            int gn = ctaBase + n;
            if (gn >= nodeEnd) break;

            // Coalesced 4B index load per lane (L1-hit on phases 1..3).
            int my = __ldg(&idx[(size_t)gn * K + lane]);

            float4 a = make_float4(0.f, 0.f, 0.f, 0.f);
            #pragma unroll
            for (int k = 0; k < K; ++k) {
                int r = __shfl_sync(0xffffffffu, my, k);   // warp-uniform
                if (r >= lo && r < hi) {                    // uniform predicate
                    const float4* row =
                        reinterpret_cast<const float4*>(tab + (size_t)r * D);
                    float4 v = __ldg(&row[lane]);           // 512B coalesced row
                    a.x += v.x; a.y += v.y; a.z += v.z; a.w += v.w;
                }
            }
            // Warp exclusively owns this node's accumulator: plain RMW.
            float4* s = &sacc[n * 32 + lane];
            float4 c = *s;
            c.x += a.x; c.y += a.y; c.z += a.z; c.w += a.w;
            *s = c;
        }
        __syncthreads();   // keep CTA (and chip, approximately) phase-aligned
    }

    // Scale and write out.
    const float sc = 1.0f / (float)K;
    for (int n = w; n < NPC; n += THREADS / 32) {
        int gn = ctaBase + n;
        if (gn >= nodeEnd) break;
        float4 a = sacc[n * 32 + lane];
        a.x *= sc; a.y *= sc; a.z *= sc; a.w *= sc;
        reinterpret_cast<float4*>(out + (size_t)gn * D)[lane] = a;
    }
}

extern "C" void kernel_launch(void* const* d_in, const int* in_sizes, int n_in,
                              void* d_out, int out_size)
{
    // Identify inputs by element count (robust to metadata ordering):
    // embed_table: 64,000,000 ; neigh_idx: 3,200,000 ; num_sample: 1
    long long max_sz = -1, mid_sz = -1;
    int ti = 0, ii = 1;
    for (int i = 0; i < n_in; ++i)
        if (in_sizes[i] > max_sz) { max_sz = in_sizes[i]; ti = i; }
    for (int i = 0; i < n_in; ++i)
        if (i != ti && in_sizes[i] > mid_sz) { mid_sz = in_sizes[i]; ii = i; }

    const float* tab = (const float*)d_in[ti];
    const int*   idx = (const int*)d_in[ii];
    float*       out = (float*)d_out;

    int B = out_size / D;                   // 100000
    int N = (int)(max_sz / D);              // 500000 table rows

    size_t smem = (size_t)NPC * 32 * sizeof(float4);   // 86,528 B
    cudaFuncSetAttribute(mean_agg_phased,
                         cudaFuncAttributeMaxDynamicSharedMemorySize,
                         (int)smem);

    // Two sequential halves: each half's accumulators fit on-chip in one wave.
    int half0_end = (B + 1) / 2;
    int ranges[2][2] = { {0, half0_end}, {half0_end, B} };

    for (int h = 0; h < 2; ++h) {
        int base = ranges[h][0], end = ranges[h][1];
        int count = end - base;
        if (count <= 0) continue;
        int grid = (count + NPC - 1) / NPC;            // 296 for 50000 nodes
        mean_agg_phased<<<grid, THREADS, smem>>>(tab, idx, out, base, end, N);
    }
}

// round 7
// speedup vs baseline: 1.2201x; 1.2201x over previous
#include <cuda_runtime.h>
#include <cstdint>

// MeanAggregatorHead: out[b,:] = (1/K) * sum_k tab[idx[b,k],:]
// B=100000, K=32, N=500000, D=128, fp32 table, int32 indices.
//
// P=2 table-chunked passes (64-128MB chunk L2-resident per pass) with:
//  - ballot mask-compaction: no per-k branches, only useful loads issue
//  - 2 nodes per warp: ~32 LDG.128 in flight per warp (MLP-saturating)
//  - pass 1 accumulates into out via red.global.add.v4.f32 (single writer
//    per element -> deterministic; skips the 51MB partial re-read)

constexpr int K = 32;
constexpr int D = 128;

__device__ __forceinline__ void red_add_f4(float4* p, float4 v) {
    asm volatile("red.global.add.v4.f32 [%0], {%1,%2,%3,%4};"
                 :: "l"(p), "f"(v.x), "f"(v.y), "f"(v.z), "f"(v.w) : "memory");
}

template <int RESIDUAL>
__global__ __launch_bounds__(256) void mean_agg_pass(
    const float* __restrict__ tab,
    const int*   __restrict__ idx,
    float* __restrict__ out,
    int nPairs, int B, int lo, int hi)
{
    int gtid = blockIdx.x * blockDim.x + threadIdx.x;
    int warp = gtid >> 5;
    int lane = gtid & 31;
    if (warp >= nPairs) return;

    int nodeA = 2 * warp;
    int nodeB = 2 * warp + 1;
    bool hasB = (nodeB < B);

    // Coalesced 4B index loads, one per lane per node.
    int idxA = __ldg(&idx[(size_t)nodeA * K + lane]);
    int idxB = hasB ? __ldg(&idx[(size_t)nodeB * K + lane]) : 0;

    // In-chunk membership masks (branch-free inner loops below).
    unsigned mA = __ballot_sync(0xffffffffu, idxA >= lo && idxA < hi);
    unsigned mB = hasB ? __ballot_sync(0xffffffffu, idxB >= lo && idxB < hi) : 0u;

    float4 aA = make_float4(0.f, 0.f, 0.f, 0.f);
    float4 aB = make_float4(0.f, 0.f, 0.f, 0.f);

    while (mA) {
        int j = __ffs(mA) - 1;  mA &= mA - 1;
        int r = __shfl_sync(0xffffffffu, idxA, j);
        float4 v = __ldg(&reinterpret_cast<const float4*>(tab + (size_t)r * D)[lane]);
        aA.x += v.x; aA.y += v.y; aA.z += v.z; aA.w += v.w;
    }
    while (mB) {
        int j = __ffs(mB) - 1;  mB &= mB - 1;
        int r = __shfl_sync(0xffffffffu, idxB, j);
        float4 v = __ldg(&reinterpret_cast<const float4*>(tab + (size_t)r * D)[lane]);
        aB.x += v.x; aB.y += v.y; aB.z += v.z; aB.w += v.w;
    }

    const float s = 1.0f / (float)K;
    aA.x *= s; aA.y *= s; aA.z *= s; aA.w *= s;
    aB.x *= s; aB.y *= s; aB.z *= s; aB.w *= s;

    float4* oA = &reinterpret_cast<float4*>(out + (size_t)nodeA * D)[lane];
    float4* oB = &reinterpret_cast<float4*>(out + (size_t)nodeB * D)[lane];

    if (RESIDUAL) {
        red_add_f4(oA, aA);            // add onto pass-0 partial, no read
        if (hasB) red_add_f4(oB, aB);
    } else {
        *oA = aA;                       // pass 0: plain scaled-partial store
        if (hasB) *oB = aB;
    }
}

extern "C" void kernel_launch(void* const* d_in, const int* in_sizes, int n_in,
                              void* d_out, int out_size)
{
    // Identify inputs by element count (robust to metadata ordering):
    // embed_table: 64,000,000 ; neigh_idx: 3,200,000 ; num_sample: 1
    long long max_sz = -1, mid_sz = -1;
    int ti = 0, ii = 1;
    for (int i = 0; i < n_in; ++i)
        if (in_sizes[i] > max_sz) { max_sz = in_sizes[i]; ti = i; }
    for (int i = 0; i < n_in; ++i)
        if (i != ti && in_sizes[i] > mid_sz) { mid_sz = in_sizes[i]; ii = i; }

    const float* tab = (const float*)d_in[ti];
    const int*   idx = (const int*)d_in[ii];
    float*       out = (float*)d_out;

    int B = out_size / D;                    // 100000
    int N = (int)(max_sz / D);               // 500000 table rows
    int split = N / 2;                       // 128MB / 128MB chunks

    int nPairs = (B + 1) / 2;                // 2 nodes per warp
    int threads = 256;                       // 8 warps/block
    long long total_threads = (long long)nPairs * 32;
    int blocks = (int)((total_threads + threads - 1) / threads);

    // Pass 0: rows [0, split)  -> out = scaled partial (store)
    mean_agg_pass<0><<<blocks, threads>>>(tab, idx, out, nPairs, B, 0, split);
    // Pass 1: rows [split, N)  -> out += scaled partial (red.add)
    mean_agg_pass<1><<<blocks, threads>>>(tab, idx, out, nPairs, B, split, N);
}

// round 8
// speedup vs baseline: 1.4259x; 1.1687x over previous
#include <cuda_runtime.h>
#include <cstdint>

// MeanAggregatorHead: out[b,:] = (1/K) * sum_k tab[idx[b,k],:]
// B=100000, K=32, N=500000, D=128, fp32 table, int32 indices.
//
// R8: index pre-partitioning (4 table-quarter buckets, 64MB each ->
// L2-resident per pass) + dense unrolled gather passes (every load useful,
// 4 LDG.128 front-batched per iteration) + red.global.add.v4.f32 partials
// (no partial re-reads; deterministic: single writer/elem, passes ordered).

constexpr int K       = 32;
constexpr int D       = 128;
constexpr int PASSES  = 4;
constexpr int MAX_B   = 100000;

__device__ int g_sidx[MAX_B * K];   // bucket-reordered indices (12.8MB)
__device__ int g_cnt [MAX_B];       // packed counts c0|c1<<8|c2<<16 (0.4MB)

__device__ __forceinline__ void red_add_f4(float4* p, float4 v) {
    asm volatile("red.global.add.v4.f32 [%0], {%1,%2,%3,%4};"
                 :: "l"(p), "f"(v.x), "f"(v.y), "f"(v.z), "f"(v.w) : "memory");
}

// ---------------- partition: bucket-sort each node's 32 indices ----------
__global__ __launch_bounds__(256) void partition_kernel(
    const int* __restrict__ idx, int B, int c1, int c2, int c3)
{
    int gtid = blockIdx.x * blockDim.x + threadIdx.x;
    int node = gtid >> 5;
    int lane = gtid & 31;
    if (node >= B) return;

    int r = __ldg(&idx[(size_t)node * K + lane]);
    int b = (r >= c1) + (r >= c2) + (r >= c3);          // bucket 0..3

    unsigned m0 = __ballot_sync(0xffffffffu, b == 0);
    unsigned m1 = __ballot_sync(0xffffffffu, b == 1);
    unsigned m2 = __ballot_sync(0xffffffffu, b == 2);
    unsigned m3 = __ballot_sync(0xffffffffu, b == 3);
    int n0 = __popc(m0), n1 = __popc(m1), n2 = __popc(m2);

    unsigned lt = (1u << lane) - 1u;
    int slot;
    if      (b == 0) slot = __popc(m0 & lt);
    else if (b == 1) slot = n0 + __popc(m1 & lt);
    else if (b == 2) slot = n0 + n1 + __popc(m2 & lt);
    else             slot = n0 + n1 + n2 + __popc(m3 & lt);

    g_sidx[(size_t)node * K + slot] = r;
    if (lane == 0) g_cnt[node] = n0 | (n1 << 8) | (n2 << 16);
}

// ---------------- gather pass PASS: dense loads over one bucket ----------
template <int PASS>
__global__ __launch_bounds__(256) void gather_pass(
    const float* __restrict__ tab, float* __restrict__ out, int B)
{
    int gtid = blockIdx.x * blockDim.x + threadIdx.x;
    int node = gtid >> 5;
    int lane = gtid & 31;
    if (node >= B) return;

    int v = g_sidx[(size_t)node * K + lane];   // reordered idx, coalesced
    int packed = g_cnt[node];                  // uniform across warp
    int n0 =  packed        & 0xff;
    int n1 = (packed >> 8)  & 0xff;
    int n2 = (packed >> 16) & 0xff;

    int start, end;
    if      (PASS == 0) { start = 0;            end = n0; }
    else if (PASS == 1) { start = n0;           end = n0 + n1; }
    else if (PASS == 2) { start = n0 + n1;      end = n0 + n1 + n2; }
    else                { start = n0 + n1 + n2; end = K; }

    float4 acc = make_float4(0.f, 0.f, 0.f, 0.f);

    int j = start;
    #pragma unroll 1
    for (; j + 4 <= end; j += 4) {             // 4 independent LDG.128 batched
        int r0 = __shfl_sync(0xffffffffu, v, j);
        int r1 = __shfl_sync(0xffffffffu, v, j + 1);
        int r2 = __shfl_sync(0xffffffffu, v, j + 2);
        int r3 = __shfl_sync(0xffffffffu, v, j + 3);
        float4 a0 = __ldg(&reinterpret_cast<const float4*>(tab + (size_t)r0 * D)[lane]);
        float4 a1 = __ldg(&reinterpret_cast<const float4*>(tab + (size_t)r1 * D)[lane]);
        float4 a2 = __ldg(&reinterpret_cast<const float4*>(tab + (size_t)r2 * D)[lane]);
        float4 a3 = __ldg(&reinterpret_cast<const float4*>(tab + (size_t)r3 * D)[lane]);
        acc.x += a0.x + a1.x + a2.x + a3.x;
        acc.y += a0.y + a1.y + a2.y + a3.y;
        acc.z += a0.z + a1.z + a2.z + a3.z;
        acc.w += a0.w + a1.w + a2.w + a3.w;
    }
    #pragma unroll 1
    for (; j < end; ++j) {
        int r = __shfl_sync(0xffffffffu, v, j);
        float4 a = __ldg(&reinterpret_cast<const float4*>(tab + (size_t)r * D)[lane]);
        acc.x += a.x; acc.y += a.y; acc.z += a.z; acc.w += a.w;
    }

    const float s = 1.0f / (float)K;
    acc.x *= s; acc.y *= s; acc.z *= s; acc.w *= s;

    float4* op = &reinterpret_cast<float4*>(out + (size_t)node * D)[lane];
    if (PASS == 0) *op = acc;                  // overwrite (graph-replay safe)
    else           red_add_f4(op, acc);        // ordered passes -> deterministic
}

extern "C" void kernel_launch(void* const* d_in, const int* in_sizes, int n_in,
                              void* d_out, int out_size)
{
    // Identify inputs by element count (robust to metadata ordering):
    // embed_table: 64,000,000 ; neigh_idx: 3,200,000 ; num_sample: 1
    long long max_sz = -1, mid_sz = -1;
    int ti = 0, ii = 1;
    for (int i = 0; i < n_in; ++i)
        if (in_sizes[i] > max_sz) { max_sz = in_sizes[i]; ti = i; }
    for (int i = 0; i < n_in; ++i)
        if (i != ti && in_sizes[i] > mid_sz) { mid_sz = in_sizes[i]; ii = i; }

    const float* tab = (const float*)d_in[ti];
    const int*   idx = (const int*)d_in[ii];
    float*       out = (float*)d_out;

    int B = out_size / D;                    // 100000
    int N = (int)(max_sz / D);               // 500000 table rows
    int chunk = (N + PASSES - 1) / PASSES;   // 125000 rows = 64MB

    int threads = 256;
    long long tt = (long long)B * 32;
    int blocks = (int)((tt + threads - 1) / threads);

    partition_kernel<<<blocks, threads>>>(idx, B, chunk, 2 * chunk, 3 * chunk);
    gather_pass<0><<<blocks, threads>>>(tab, out, B);
    gather_pass<1><<<blocks, threads>>>(tab, out, B);
    gather_pass<2><<<blocks, threads>>>(tab, out, B);
    gather_pass<3><<<blocks, threads>>>(tab, out, B);
}